// round 14
// baseline (speedup 1.0000x reference)
#include <cuda_runtime.h>
#include <cuda_fp16.h>
#include <math.h>

#define NK 512

// ---- scratch (static __device__ arrays; no allocations anywhere) ----
// Transposed features, pixel-major [p][c], stored fp16 (halves L2 traffic).
static __device__ __align__(16) __half g_ft0[192 * 96 * 96];
static __device__ __align__(16) __half g_ft1[384 * 48 * 48];
static __device__ __align__(16) __half g_ft2[768 * 24 * 24];
static __device__ __align__(16) __half g_ft3[1536 * 12 * 12];
static __device__ float g_Ry[NK][4][96];        // per-box per-level row weights (norm folded in)
static __device__ float g_Rx[NK][4][96];        // per-box per-level col weights
static __device__ int   g_bnd[NK][4][4];        // ylo, yhi(excl), xlo, xhi(excl)

// ------------------------------------------------------------------
// Per-axis ROI-align weight for one output index `idx` (0..L-1).
// Mirrors the reference _axis_samples exactly (adaptive grid mask,
// oob -> drop sample, clamp-to-0 low side, hi-edge collapse).
// ------------------------------------------------------------------
__device__ __forceinline__ float axis_w(int idx, float lo, float size, float grid, int L) {
    float b = size / 7.0f;
    float step = b / grid;
    float acc = 0.0f;
#pragma unroll
    for (int p = 0; p < 7; ++p) {
#pragma unroll
        for (int s = 0; s < 8; ++s) {
            if ((float)s >= grid) continue;                  // adaptive sampling grid mask
            float coord = lo + (float)p * b + ((float)s + 0.5f) * step;
            if (coord < -1.0f || coord > (float)L) continue; // whole sample dropped
            float c = fmaxf(coord, 0.0f);
            int i0 = (int)floorf(c);
            int i1; float f;
            if (i0 >= L - 1) { i0 = L - 1; i1 = L - 1; f = 0.0f; }
            else             { i1 = i0 + 1; f = c - (float)i0; }
            if (i0 == idx) acc += 1.0f - f;
            if (i1 == idx) acc += f;
        }
    }
    return acc;
}

// ------------------------------------------------------------------
// Prep kernel (fused): blocks [0, 3264) transpose+convert the four
// feature levels [C,P] fp32 -> [P,C] fp16; blocks [3264, 3776) build
// per-box separable ROI weights + upsample-adjoint pullback + spans.
// ------------------------------------------------------------------
__global__ __launch_bounds__(256) void prep_kernel(
    const float* __restrict__ in0, const float* __restrict__ in1,
    const float* __restrict__ in2, const float* __restrict__ in3,
    const float* __restrict__ boxes) {

    if (blockIdx.x < 3264) {
        // ---------------- transpose branch ----------------
        int b = blockIdx.x;
        const float* in; __half* outp; int C, P, ptiles;
        if (b < 1728)      { in = in0; outp = g_ft0; C = 192;  P = 9216; ptiles = 288; }
        else if (b < 2592) { in = in1; outp = g_ft1; C = 384;  P = 2304; ptiles = 72;  b -= 1728; }
        else if (b < 3024) { in = in2; outp = g_ft2; C = 768;  P = 576;  ptiles = 18;  b -= 2592; }
        else               { in = in3; outp = g_ft3; C = 1536; P = 144;  ptiles = 5;   b -= 3024; }

        __shared__ float tile[32][33];
        const int p0 = (b % ptiles) * 32, c0 = (b / ptiles) * 32;
        const int tx = threadIdx.x & 31, ty = threadIdx.x >> 5;   // 32 x 8
#pragma unroll
        for (int i = ty; i < 32; i += 8) {
            int c = c0 + i, p = p0 + tx;
            if (c < C && p < P) tile[i][tx] = in[(size_t)c * P + p];
        }
        __syncthreads();
#pragma unroll
        for (int i = ty; i < 32; i += 8) {
            int p = p0 + i, c = c0 + tx;
            if (p < P && c < C) outp[(size_t)p * C + c] = __float2half_rn(tile[tx][i]);
        }
        return;
    }

    // ---------------- weight branch ----------------
    const int k = blockIdx.x - 3264;
    const int t = threadIdx.x;   // lanes >= 128 idle but join barriers

    __shared__ float sY[96], sX[96];
    __shared__ int bb[4][4];   // per-level: {ylo, yhi_incl, xlo, xhi_incl}
    if (t < 16) bb[t >> 2][t & 3] = (t & 1) ? -1 : (1 << 20);

    const float x1 = boxes[k * 4 + 0];
    const float y1 = boxes[k * 4 + 1];
    const float x2 = boxes[k * 4 + 2];
    const float y2 = boxes[k * 4 + 3];
    const float rw = fmaxf(x2 - x1, 1.0f);
    const float rh = fmaxf(y2 - y1, 1.0f);
    const float gw = fminf(fmaxf(ceilf(rw / 7.0f), 1.0f), 8.0f);
    const float gh = fminf(fmaxf(ceilf(rh / 7.0f), 1.0f), 8.0f);
    const float norm = 1.0f / (gh * gw * 49.0f);
    __syncthreads();

    if (t < 96) {
        float vy = axis_w(t, y1, rh, gh, 96) * norm;   // fold norm into Ry
        float vx = axis_w(t, x1, rw, gw, 96);
        sY[t] = vy; sX[t] = vx;
        g_Ry[k][0][t] = vy; g_Rx[k][0][t] = vx;
        if (vy > 0.0f) { atomicMin(&bb[0][0], t); atomicMax(&bb[0][1], t); }
        if (vx > 0.0f) { atomicMin(&bb[0][2], t); atomicMax(&bb[0][3], t); }
    }
    __syncthreads();

    // Pull back 96 -> H_l through the half-pixel 2-tap bilinear adjoint
    // (clamped form == jax.image.resize's renormalized triangle kernel
    // at edges; antialias is a no-op for upscaling). Source window
    // [(t-1)<<l, (t+2)<<l) provably covers all contributing taps.
#pragma unroll
    for (int l = 1; l <= 3; ++l) {
        const int H = 96 >> l;
        if (t < H) {
            float ay = 0.0f, ax = 0.0f;
            const float scale = (float)H / 96.0f;
            const int ylo = max(0, (t - 1) << l);
            const int yhi = min(96, (t + 2) << l);
            for (int y = ylo; y < yhi; ++y) {
                float src = (y + 0.5f) * scale - 0.5f;
                int i0 = (int)floorf(src);
                float f = src - (float)i0;
                int j0 = min(max(i0, 0), H - 1);
                int j1 = min(max(i0 + 1, 0), H - 1);
                float wy = sY[y], wx = sX[y];
                if (j0 == t) { ay += wy * (1.0f - f); ax += wx * (1.0f - f); }
                if (j1 == t) { ay += wy * f;          ax += wx * f; }
            }
            g_Ry[k][l][t] = ay; g_Rx[k][l][t] = ax;
            if (ay > 0.0f) { atomicMin(&bb[l][0], t); atomicMax(&bb[l][1], t); }
            if (ax > 0.0f) { atomicMin(&bb[l][2], t); atomicMax(&bb[l][3], t); }
        }
    }
    __syncthreads();

    if (t < 16) {
        int l = t >> 2, j = t & 3;
        int v = bb[l][j];
        if (j == 1 || j == 3) v += 1;   // exclusive hi
        g_bnd[k][l][j] = v;
    }
}

// ------------------------------------------------------------------
// Kernel M: out[k, c] = sum_y Ry[y] * sum_x Rx[x] * feat_h[y, x, c]
// grid = (512 boxes, 16 chunks). Level 0 is split into two 96-channel
// chunks to halve its block weight (load balance for the last wave):
//   chunks 0-1 : level 0, 96 ch each   (12 lanes x 16 y-slices)
//   chunks 2-3 : level 1, 192 ch each  (24 lanes x  8 y-slices)
//   chunks 4-7 : level 2, 192 ch each
//   chunks 8-15: level 3, 192 ch each
// Block = 192 threads; each lane loads one uint4 (8 fp16 channels);
// fp32 accumulation; loops bounded to the per-box nonzero span;
// x-loop unrolled x4; 32-bit inner-loop addressing. Reduction buffer
// padded to stride 9 for conflict-free smem spills.
// ------------------------------------------------------------------
__global__ __launch_bounds__(192) void mkernel(float* __restrict__ out) {
    const int k = blockIdx.x;
    const int chunk = blockIdx.y;
    int l, cb, lvbase, Cch;
    if (chunk < 2)      { l = 0; cb = chunk * 96;        lvbase = 0;    Cch = 96;  }
    else if (chunk < 4) { l = 1; cb = (chunk - 2) * 192; lvbase = 192;  Cch = 192; }
    else if (chunk < 8) { l = 2; cb = (chunk - 4) * 192; lvbase = 576;  Cch = 192; }
    else                { l = 3; cb = (chunk - 8) * 192; lvbase = 1344; Cch = 192; }

    const __half* ft; int Hh, C;
    if (l == 0)      { ft = g_ft0; Hh = 96; C = 192;  }
    else if (l == 1) { ft = g_ft1; Hh = 48; C = 384;  }
    else if (l == 2) { ft = g_ft2; Hh = 24; C = 768;  }
    else             { ft = g_ft3; Hh = 12; C = 1536; }
    const int Wd = Hh;

    const int nlan = Cch >> 3;        // 12 or 24 lanes
    const int ng   = 192 / nlan;      // 16 or 8 y-slices

    const int t = threadIdx.x;
    const int lane = t % nlan;        // 8-channel group
    const int yg = t / nlan;          // y-slice

    __shared__ float sRy[96], sRx[96];
    __shared__ int bnd[4];
    __shared__ float red[192][9];     // stride-9 padding: conflict-free spills
    if (t < Hh) { sRy[t] = g_Ry[k][l][t]; sRx[t] = g_Rx[k][l][t]; }
    if (t >= 96 && t < 100) bnd[t - 96] = g_bnd[k][l][t - 96];
    __syncthreads();

    const int ylo = bnd[0], yhi = bnd[1], xlo = bnd[2], xhi = bnd[3];
    const __half* base = ft + cb + lane * 8;

    float acc[8];
#pragma unroll
    for (int i = 0; i < 8; ++i) acc[i] = 0.0f;

    for (int y = ylo + yg; y < yhi; y += ng) {
        float wy = sRy[y];
        if (wy == 0.0f) continue;
        const __half* row = base + y * Wd * C;   // 32-bit offset chain
        int x = xlo;
        for (; x + 3 < xhi; x += 4) {
            int o0 = x * C;
            float w0 = wy * sRx[x];
            float w1 = wy * sRx[x + 1];
            float w2 = wy * sRx[x + 2];
            float w3 = wy * sRx[x + 3];
            uint4 v0 = *(const uint4*)(row + o0);
            uint4 v1 = *(const uint4*)(row + o0 + C);
            uint4 v2 = *(const uint4*)(row + o0 + 2 * C);
            uint4 v3 = *(const uint4*)(row + o0 + 3 * C);
            const __half2* h0 = (const __half2*)&v0;
            const __half2* h1 = (const __half2*)&v1;
            const __half2* h2 = (const __half2*)&v2;
            const __half2* h3 = (const __half2*)&v3;
#pragma unroll
            for (int j = 0; j < 4; ++j) {
                float2 f0 = __half22float2(h0[j]);
                float2 f1 = __half22float2(h1[j]);
                float2 f2 = __half22float2(h2[j]);
                float2 f3 = __half22float2(h3[j]);
                acc[2 * j + 0] = fmaf(w0, f0.x, acc[2 * j + 0]);
                acc[2 * j + 1] = fmaf(w0, f0.y, acc[2 * j + 1]);
                acc[2 * j + 0] = fmaf(w1, f1.x, acc[2 * j + 0]);
                acc[2 * j + 1] = fmaf(w1, f1.y, acc[2 * j + 1]);
                acc[2 * j + 0] = fmaf(w2, f2.x, acc[2 * j + 0]);
                acc[2 * j + 1] = fmaf(w2, f2.y, acc[2 * j + 1]);
                acc[2 * j + 0] = fmaf(w3, f3.x, acc[2 * j + 0]);
                acc[2 * j + 1] = fmaf(w3, f3.y, acc[2 * j + 1]);
            }
        }
        for (; x < xhi; ++x) {
            float w = wy * sRx[x];
            uint4 v = *(const uint4*)(row + x * C);
            const __half2* h = (const __half2*)&v;
#pragma unroll
            for (int j = 0; j < 4; ++j) {
                float2 f = __half22float2(h[j]);
                acc[2 * j + 0] = fmaf(w, f.x, acc[2 * j + 0]);
                acc[2 * j + 1] = fmaf(w, f.y, acc[2 * j + 1]);
            }
        }
    }
#pragma unroll
    for (int i = 0; i < 8; ++i) red[t][i] = acc[i];
    __syncthreads();

    // thread c (< Cch) owns output channel c within this chunk:
    // sum partials from all ng y-slice groups of its lane.
    if (t < Cch) {
        const int ln = t >> 3, ch = t & 7;
        float s = 0.0f;
        for (int g = 0; g < ng; ++g) s += red[g * nlan + ln][ch];
        out[(size_t)k * 2880 + lvbase + cb + t] = s;
    }
}

extern "C" void kernel_launch(void* const* d_in, const int* in_sizes, int n_in,
                              void* d_out, int out_size) {
    const float* f0    = (const float*)d_in[0];  // [1,192,96,96]
    const float* f1    = (const float*)d_in[1];  // [1,384,48,48]
    const float* f2    = (const float*)d_in[2];  // [1,768,24,24]
    const float* f3    = (const float*)d_in[3];  // [1,1536,12,12]
    const float* boxes = (const float*)d_in[4];  // [512,4]
    float* out = (float*)d_out;                  // [1,512,2880]
    (void)in_sizes; (void)n_in; (void)out_size;

    prep_kernel<<<3264 + NK, 256>>>(f0, f1, f2, f3, boxes);
    mkernel<<<dim3(NK, 16), 192>>>(out);
}

// round 17
// speedup vs baseline: 1.2247x; 1.2247x over previous
#include <cuda_runtime.h>
#include <cuda_fp16.h>
#include <math.h>

#define NK 512

// ---- static scratch (no allocations anywhere) ----
// Dense per-box ROI weight matrices, fp16, K-major per box.
static __device__ __align__(16) __half g_W0[NK * 9216];   // level 0: P=96*96
static __device__ __align__(16) __half g_W1[NK * 2304];   // level 1: P=48*48
static __device__ __align__(16) __half g_W2[NK * 576];    // level 2: P=24*24
static __device__ __align__(16) __half g_W3[NK * 160];    // level 3: P=144 pad 160
// Features fp16 in native [c][p] layout (K-innermost, no transpose needed).
static __device__ __align__(16) __half g_F0[192 * 9216];
static __device__ __align__(16) __half g_F1[384 * 2304];
static __device__ __align__(16) __half g_F2[768 * 576];
static __device__ __align__(16) __half g_F3[1536 * 160];  // K padded 144->160 (zeros)
// Split-K partial sums (deterministic reduce, no fp atomics).
static __device__ float g_p0[8 * NK * 192];
static __device__ float g_p1[2 * NK * 384];

// ------------------------------------------------------------------
// Per-axis ROI-align weight for one output index (0..L-1). Mirrors the
// reference _axis_samples exactly (adaptive grid mask, oob drop,
// low-side clamp, hi-edge collapse).
// ------------------------------------------------------------------
__device__ __forceinline__ float axis_w(int idx, float lo, float size, float grid, int L) {
    float b = size / 7.0f;
    float step = b / grid;
    float acc = 0.0f;
#pragma unroll
    for (int p = 0; p < 7; ++p) {
#pragma unroll
        for (int s = 0; s < 8; ++s) {
            if ((float)s >= grid) continue;
            float coord = lo + (float)p * b + ((float)s + 0.5f) * step;
            if (coord < -1.0f || coord > (float)L) continue;
            float c = fmaxf(coord, 0.0f);
            int i0 = (int)floorf(c);
            int i1; float f;
            if (i0 >= L - 1) { i0 = L - 1; i1 = L - 1; f = 0.0f; }
            else             { i1 = i0 + 1; f = c - (float)i0; }
            if (i0 == idx) acc += 1.0f - f;
            if (i1 == idx) acc += f;
        }
    }
    return acc;
}

// ------------------------------------------------------------------
// prep (fused):
//   blocks [0, 512)    : per-box separable weights -> dense fp16 W rows
//                        (level-0 weights pulled back to levels 1-3 via
//                        the bilinear-upsample adjoint; clamped 2-tap ==
//                        jax renormalized triangle kernel at edges)
//   blocks [512, 7040) : feature convert fp32 -> fp16, layout [c][p]
//                        (level 3 K padded to 160 with zeros)
// ------------------------------------------------------------------
__global__ __launch_bounds__(256) void prep_kernel(
    const float* __restrict__ in0, const float* __restrict__ in1,
    const float* __restrict__ in2, const float* __restrict__ in3,
    const float* __restrict__ boxes) {

    const int t = threadIdx.x;
    if (blockIdx.x < NK) {
        // ---------------- weight branch ----------------
        const int k = blockIdx.x;
        __shared__ float sRy[4][96], sRx[4][96];

        const float x1 = boxes[k * 4 + 0];
        const float y1 = boxes[k * 4 + 1];
        const float x2 = boxes[k * 4 + 2];
        const float y2 = boxes[k * 4 + 3];
        const float rw = fmaxf(x2 - x1, 1.0f);
        const float rh = fmaxf(y2 - y1, 1.0f);
        const float gw = fminf(fmaxf(ceilf(rw / 7.0f), 1.0f), 8.0f);
        const float gh = fminf(fmaxf(ceilf(rh / 7.0f), 1.0f), 8.0f);
        const float norm = 1.0f / (gh * gw * 49.0f);

        if (t < 96) {
            sRy[0][t] = axis_w(t, y1, rh, gh, 96) * norm;   // norm folded into Ry
            sRx[0][t] = axis_w(t, x1, rw, gw, 96);
        }
        __syncthreads();

#pragma unroll
        for (int l = 1; l <= 3; ++l) {
            const int H = 96 >> l;
            if (t < H) {
                float ay = 0.0f, ax = 0.0f;
                const float scale = (float)H / 96.0f;
                const int ylo = max(0, (t - 1) << l);
                const int yhi = min(96, (t + 2) << l);
                for (int y = ylo; y < yhi; ++y) {
                    float src = (y + 0.5f) * scale - 0.5f;
                    int i0 = (int)floorf(src);
                    float f = src - (float)i0;
                    int j0 = min(max(i0, 0), H - 1);
                    int j1 = min(max(i0 + 1, 0), H - 1);
                    float wy = sRy[0][y], wx = sRx[0][y];
                    if (j0 == t) { ay += wy * (1.0f - f); ax += wx * (1.0f - f); }
                    if (j1 == t) { ay += wy * f;          ax += wx * f; }
                }
                sRy[l][t] = ay; sRx[l][t] = ax;
            }
        }
        __syncthreads();

        // Dense W rows, half2 pair writes (row widths even -> pairs stay in row).
        {   __half* W = g_W0 + (size_t)k * 9216;
            for (int p = 2 * t; p < 9216; p += 512) {
                int y = p / 96, x = p - y * 96;
                float ry = sRy[0][y];
                *(__half2*)&W[p] = __floats2half2_rn(ry * sRx[0][x], ry * sRx[0][x + 1]);
            }
        }
        {   __half* W = g_W1 + (size_t)k * 2304;
            for (int p = 2 * t; p < 2304; p += 512) {
                int y = p / 48, x = p - y * 48;
                float ry = sRy[1][y];
                *(__half2*)&W[p] = __floats2half2_rn(ry * sRx[1][x], ry * sRx[1][x + 1]);
            }
        }
        {   __half* W = g_W2 + (size_t)k * 576;
            for (int p = 2 * t; p < 576; p += 512) {
                int y = p / 24, x = p - y * 24;
                float ry = sRy[2][y];
                *(__half2*)&W[p] = __floats2half2_rn(ry * sRx[2][x], ry * sRx[2][x + 1]);
            }
        }
        {   __half* W = g_W3 + (size_t)k * 160;
            for (int p = 2 * t; p < 160; p += 512) {
                int y = p / 12, x = p - y * 12;
                __half2 v;
                if (y < 12) {
                    float ry = sRy[3][y];
                    v = __floats2half2_rn(ry * sRx[3][x], ry * sRx[3][x + 1]);
                } else v = __floats2half2_rn(0.0f, 0.0f);
                *(__half2*)&W[p] = v;
            }
        }
        return;
    }

    // ---------------- feature-convert branch ----------------
    // half2 units: l0 884736 | l1 442368 | l2 221184 | l3 122880 = 1,671,168
    int idx = (blockIdx.x - NK) * 256 + t;
    if (idx < 884736) {
        int e = idx * 2;
        float2 v = *(const float2*)&in0[e];
        *(__half2*)&g_F0[e] = __floats2half2_rn(v.x, v.y);
    } else if (idx < 1327104) {
        int e = (idx - 884736) * 2;
        float2 v = *(const float2*)&in1[e];
        *(__half2*)&g_F1[e] = __floats2half2_rn(v.x, v.y);
    } else if (idx < 1548288) {
        int e = (idx - 1327104) * 2;
        float2 v = *(const float2*)&in2[e];
        *(__half2*)&g_F2[e] = __floats2half2_rn(v.x, v.y);
    } else {
        int e = (idx - 1548288) * 2;      // element index in padded [c][160]
        int c = e / 160, p = e - c * 160;
        __half2 v;
        if (p < 144) {
            float2 f = *(const float2*)&in3[c * 144 + p];
            v = __floats2half2_rn(f.x, f.y);
        } else v = __floats2half2_rn(0.0f, 0.0f);
        *(__half2*)&g_F3[e] = v;
    }
}

// ------------------------------------------------------------------
// gemm_all: merged per-level GEMMs out[512,N] = W[512,Kp] x F[N,Kp]^T,
// fp16 in / fp32 acc, BM=BN=64, BK=32, 128 threads (2x2 warps, each
// 32x32 via 2x4 m16n8k16). Both operands K-innermost -> straight uint4
// staging into padded smem (stride 40: fragment LDS provably
// conflict-free). Level decode by block range; heavy split-K levels
// first for wave balance:
//   [0,192)   level 0: 8 x 3 x 8 split-K  -> g_p0
//   [192,288) level 1: 8 x 6 x 2 split-K  -> g_p1
//   [288,384) level 2: 8 x 12             -> out direct
//   [384,576) level 3: 8 x 24             -> out direct
// ------------------------------------------------------------------
__global__ __launch_bounds__(128) void gemm_all(float* __restrict__ outp) {
    int b = blockIdx.x;
    const __half *A, *Bf;
    int Kp, Kchunk, Nlvl, lvbase, bx, by, bz;
    float* part;
    if (b < 192) {
        A = g_W0; Bf = g_F0; Kp = 9216; Kchunk = 1152; Nlvl = 192; lvbase = 0;
        bx = b & 7; int r = b >> 3; by = r % 3; bz = r / 3; part = g_p0;
    } else if (b < 288) {
        b -= 192;
        A = g_W1; Bf = g_F1; Kp = 2304; Kchunk = 1152; Nlvl = 384; lvbase = 192;
        bx = b & 7; int r = b >> 3; by = r % 6; bz = r / 6; part = g_p1;
    } else if (b < 384) {
        b -= 288;
        A = g_W2; Bf = g_F2; Kp = 576; Kchunk = 576; Nlvl = 768; lvbase = 576;
        bx = b & 7; by = b >> 3; bz = 0; part = nullptr;
    } else {
        b -= 384;
        A = g_W3; Bf = g_F3; Kp = 160; Kchunk = 160; Nlvl = 1536; lvbase = 1344;
        bx = b & 7; by = b >> 3; bz = 0; part = nullptr;
    }

    const int m0 = bx * 64;
    const int n0 = by * 64;
    const int kbeg = bz * Kchunk;

    __shared__ __half As[64][40];
    __shared__ __half Bs[64][40];

    const int tid = threadIdx.x;
    const int lane = tid & 31, warp = tid >> 5;
    const int wm = warp >> 1, wn = warp & 1;       // 2x2 warp grid
    const int g = lane >> 2, t2 = (lane & 3) << 1; // fragment coords

    float d[2][4][4];
#pragma unroll
    for (int mf = 0; mf < 2; ++mf)
#pragma unroll
        for (int nf = 0; nf < 4; ++nf)
#pragma unroll
            for (int i = 0; i < 4; ++i) d[mf][nf][i] = 0.0f;

    for (int kb = kbeg; kb < kbeg + Kchunk; kb += 32) {
#pragma unroll
        for (int i = 0; i < 2; ++i) {
            int lin = tid + i * 128;
            int r = lin >> 2, s = lin & 3;
            *(uint4*)&As[r][s * 8] = *(const uint4*)&A[(size_t)(m0 + r) * Kp + kb + s * 8];
            *(uint4*)&Bs[r][s * 8] = *(const uint4*)&Bf[(size_t)(n0 + r) * Kp + kb + s * 8];
        }
        __syncthreads();

#pragma unroll
        for (int kk = 0; kk < 32; kk += 16) {
            unsigned a[2][4], bfr[4][2];
#pragma unroll
            for (int mf = 0; mf < 2; ++mf) {
                int mb = wm * 32 + mf * 16;
                a[mf][0] = *(const unsigned*)&As[mb + g][kk + t2];
                a[mf][1] = *(const unsigned*)&As[mb + 8 + g][kk + t2];
                a[mf][2] = *(const unsigned*)&As[mb + g][kk + 8 + t2];
                a[mf][3] = *(const unsigned*)&As[mb + 8 + g][kk + 8 + t2];
            }
#pragma unroll
            for (int nf = 0; nf < 4; ++nf) {
                int nb = wn * 32 + nf * 8;
                bfr[nf][0] = *(const unsigned*)&Bs[nb + g][kk + t2];
                bfr[nf][1] = *(const unsigned*)&Bs[nb + g][kk + 8 + t2];
            }
#pragma unroll
            for (int mf = 0; mf < 2; ++mf)
#pragma unroll
                for (int nf = 0; nf < 4; ++nf) {
                    asm volatile(
                        "mma.sync.aligned.m16n8k16.row.col.f32.f16.f16.f32 "
                        "{%0,%1,%2,%3}, {%4,%5,%6,%7}, {%8,%9}, {%0,%1,%2,%3};"
                        : "+f"(d[mf][nf][0]), "+f"(d[mf][nf][1]),
                          "+f"(d[mf][nf][2]), "+f"(d[mf][nf][3])
                        : "r"(a[mf][0]), "r"(a[mf][1]), "r"(a[mf][2]), "r"(a[mf][3]),
                          "r"(bfr[nf][0]), "r"(bfr[nf][1]));
                }
        }
        __syncthreads();
    }

    // epilogue (standard D layout: d0,d1 row g cols t2,t2+1; d2,d3 row g+8)
#pragma unroll
    for (int mf = 0; mf < 2; ++mf) {
#pragma unroll
        for (int nf = 0; nf < 4; ++nf) {
            int row = m0 + wm * 32 + mf * 16 + g;
            int col = n0 + wn * 32 + nf * 8 + t2;
            if (part == nullptr) {
                float* o0 = outp + (size_t)row * 2880 + lvbase + col;
                float* o1 = outp + (size_t)(row + 8) * 2880 + lvbase + col;
                *(float2*)o0 = make_float2(d[mf][nf][0], d[mf][nf][1]);
                *(float2*)o1 = make_float2(d[mf][nf][2], d[mf][nf][3]);
            } else {
                size_t b0 = (size_t)(bz * NK + row) * Nlvl + col;
                size_t b1 = (size_t)(bz * NK + row + 8) * Nlvl + col;
                *(float2*)&part[b0] = make_float2(d[mf][nf][0], d[mf][nf][1]);
                *(float2*)&part[b1] = make_float2(d[mf][nf][2], d[mf][nf][3]);
            }
        }
    }
}

// ------------------------------------------------------------------
// Reduce split-K partials into out: cols [0,192) sum 8 (level 0),
// cols [192,576) sum 2 (level 1). One block per box. Deterministic.
// ------------------------------------------------------------------
__global__ __launch_bounds__(256) void reduce_kernel(float* __restrict__ out) {
    const int k = blockIdx.x;
    const int t = threadIdx.x;
    for (int n = t; n < 192; n += 256) {
        float s = 0.0f;
#pragma unroll
        for (int sp = 0; sp < 8; ++sp) s += g_p0[(size_t)(sp * NK + k) * 192 + n];
        out[(size_t)k * 2880 + n] = s;
    }
    for (int n = t; n < 384; n += 256) {
        float s = g_p1[(size_t)k * 384 + n] + g_p1[(size_t)(NK + k) * 384 + n];
        out[(size_t)k * 2880 + 192 + n] = s;
    }
}

extern "C" void kernel_launch(void* const* d_in, const int* in_sizes, int n_in,
                              void* d_out, int out_size) {
    const float* f0    = (const float*)d_in[0];  // [1,192,96,96]
    const float* f1    = (const float*)d_in[1];  // [1,384,48,48]
    const float* f2    = (const float*)d_in[2];  // [1,768,24,24]
    const float* f3    = (const float*)d_in[3];  // [1,1536,12,12]
    const float* boxes = (const float*)d_in[4];  // [512,4]
    float* out = (float*)d_out;                  // [1,512,2880]
    (void)in_sizes; (void)n_in; (void)out_size;

    prep_kernel<<<NK + 6528, 256>>>(f0, f1, f2, f3, boxes);
    gemm_all<<<576, 128>>>(out);
    reduce_kernel<<<NK, 256>>>(out);
}